// round 16
// baseline (speedup 1.0000x reference)
#include <cuda_runtime.h>
#include <cuda_fp16.h>
#include <math.h>
#include <stdint.h>

// ---------------------------------------------------------------------------
// Problem constants
// ---------------------------------------------------------------------------
constexpr int B_   = 16;
constexpr int C_   = 512;
constexpr int Qn   = 1024;
constexpr int C2_  = 256;
constexpr int N1_  = 256;
constexpr int N2_  = 1024;

// ---------------------------------------------------------------------------
// Device scratch (fp32 intermediates + fp16 planes)
// ---------------------------------------------------------------------------
__device__ float g_kv1n [(size_t)2 * B_ * N1_ * C_];
__device__ float g_kv2n [(size_t)2 * B_ * N2_ * C_];
__device__ float g_kv1  [(size_t)2 * B_ * N1_ * C2_];
__device__ float g_v2   [(size_t)B_ * N2_ * C2_];

__device__ __half g_qf   [(size_t)16384 * 512];
__device__ __half g_qpf  [(size_t)16384 * 512];
__device__ __half g_imgf [(size_t)2 * B_ * C_ * 64 * 64];
__device__ __half g_kv1nf[(size_t)8192 * 512];
__device__ __half g_kv2nf[(size_t)32768 * 512];
__device__ __half g_k1pf [(size_t)8192 * 256];
__device__ __half g_k2pf [(size_t)16384 * 256];
__device__ __half g_vt1f [(size_t)B_ * C2_ * N1_];
__device__ __half g_vt2f [(size_t)B_ * C2_ * N2_];
__device__ __half g_xf   [(size_t)16384 * 512];
// weights
__device__ __half g_qwf [262144];
__device__ __half g_s1wf[4194304];
__device__ __half g_s2wf[1048576];
__device__ __half g_k1wf[131072];
__device__ __half g_k2wf[131072];
__device__ __half g_v2wf[131072];
__device__ __half g_pwf [262144];

// ---------------------------------------------------------------------------
// helpers
// ---------------------------------------------------------------------------
__device__ __forceinline__ uint32_t smem_u32(const void* p) {
    uint32_t a;
    asm("{ .reg .u64 t; cvta.to.shared.u64 t, %1; cvt.u32.u64 %0, t; }" : "=r"(a) : "l"(p));
    return a;
}
__device__ __forceinline__ void ldsm_x4(uint32_t& r0, uint32_t& r1, uint32_t& r2, uint32_t& r3,
                                        uint32_t addr) {
    asm volatile("ldmatrix.sync.aligned.m8n8.x4.shared.b16 {%0,%1,%2,%3}, [%4];"
                 : "=r"(r0), "=r"(r1), "=r"(r2), "=r"(r3) : "r"(addr));
}
__device__ __forceinline__ void mma_f16(float* d,
                                        uint32_t a0, uint32_t a1, uint32_t a2, uint32_t a3,
                                        uint32_t b0, uint32_t b1) {
    asm volatile(
        "mma.sync.aligned.m16n8k16.row.col.f32.f16.f16.f32 "
        "{%0,%1,%2,%3}, {%4,%5,%6,%7}, {%8,%9}, {%0,%1,%2,%3};"
        : "+f"(d[0]), "+f"(d[1]), "+f"(d[2]), "+f"(d[3])
        : "r"(a0), "r"(a1), "r"(a2), "r"(a3), "r"(b0), "r"(b1));
}
__device__ __forceinline__ uint32_t pack_f16(float x, float y) {
    __half2 p = __floats2half2_rn(x, y);
    return *(uint32_t*)&p;
}

#define CP_ASYNC16(dst, src) \
    asm volatile("cp.async.cg.shared.global [%0], [%1], 16;" :: "r"(dst), "l"(src) : "memory")
#define CP_ASYNC8(dst, src) \
    asm volatile("cp.async.ca.shared.global [%0], [%1], 8;" :: "r"(dst), "l"(src) : "memory")
#define CP_ASYNC4(dst, src) \
    asm volatile("cp.async.ca.shared.global [%0], [%1], 4;" :: "r"(dst), "l"(src) : "memory")
#define CP_COMMIT() asm volatile("cp.async.commit_group;" ::: "memory")
#define CP_WAIT0()  asm volatile("cp.async.wait_group 0;" ::: "memory")
#define CP_WAIT1()  asm volatile("cp.async.wait_group 1;" ::: "memory")

// ---------------------------------------------------------------------------
// fp32 -> fp16 plane
// ---------------------------------------------------------------------------
__global__ void split_h_kernel(const float* __restrict__ src,
                               __half* __restrict__ h)
{
    int i = blockIdx.x * 256 + threadIdx.x;
    float4 v = ((const float4*)src)[i];
    ((uint2*)h)[i] = make_uint2(pack_f16(v.x, v.y), pack_f16(v.z, v.w));
}

// ---------------------------------------------------------------------------
// (N,B,C) -> raw-reshape image, fp16 (K + V one launch)
// ---------------------------------------------------------------------------
__global__ void to_image_h_kernel(const float* __restrict__ srcK,
                                  const float* __restrict__ srcV,
                                  __half* __restrict__ h,
                                  size_t img1)
{
    __shared__ float sm[16][513];
    const int half_ = blockIdx.x >> 12;
    const float* src = half_ ? srcV : srcK;
    const size_t dofs = half_ ? img1 : 0;
    size_t base = (size_t)(blockIdx.x & 4095) * 8192;
    for (int j = threadIdx.x; j < 8192; j += 256) sm[j >> 9][j & 511] = src[base + j];
    __syncthreads();
    for (int r = threadIdx.x; r < 8192; r += 256) {
        h[dofs + base + r] = __float2half(sm[r & 15][r >> 4]);
    }
}

// ---------------------------------------------------------------------------
// Chunk MMA body: K-chunk 64 = 4 sequential k16 groups, single frag set
// (identical per-group code to the validated R14 loop).
// ---------------------------------------------------------------------------
#define GEMM_CHUNK_BODY64(AB, WB)                                               \
    _Pragma("unroll")                                                           \
    for (int kh = 0; kh < 4; kh++) {                                            \
        const uint32_t ko = (uint32_t)kh * 32;                                  \
        uint32_t AA[4][4], BB[4][4];                                            \
        _Pragma("unroll")                                                       \
        for (int mt = 0; mt < 4; mt++)                                          \
            ldsm_x4(AA[mt][0], AA[mt][1], AA[mt][2], AA[mt][3], (AB) + aOffs[mt] + ko); \
        _Pragma("unroll")                                                       \
        for (int nt = 0; nt < 4; nt++)                                          \
            ldsm_x4(BB[nt][0], BB[nt][1], BB[nt][2], BB[nt][3], (WB) + bOffs[nt] + ko); \
        _Pragma("unroll")                                                       \
        for (int mt = 0; mt < 4; mt++)                                          \
        _Pragma("unroll")                                                       \
        for (int nt = 0; nt < 4; nt++) {                                        \
            mma_f16(acc[mt][2 * nt + 0], AA[mt][0], AA[mt][1], AA[mt][2], AA[mt][3], BB[nt][0], BB[nt][2]); \
            mma_f16(acc[mt][2 * nt + 1], AA[mt][0], AA[mt][1], AA[mt][2], AA[mt][3], BB[nt][1], BB[nt][3]); \
        }                                                                       \
    }

// ---------------------------------------------------------------------------
// fp16 HMMA GEMM: 128 threads, 4 warps of 64x64, K-chunk 64, cp.async 2-buf.
// LOADER 0: row-major. 1: 4x4/s4 conv im2col. 2: 2x2/s2 conv.
// OUT bit0: fp32 Cmat (+bias); bit1: fp16 plane Ch.
// smem: per buf A 18432 + W 18432 = 36864; double = 73728.
// ---------------------------------------------------------------------------
template <int LOADER, int OUT>
__global__ __launch_bounds__(128, 2) void hgemm6_kernel(
    const __half* __restrict__ A, const __half* __restrict__ W,
    const float* __restrict__ bias, float* __restrict__ Cmat,
    __half* __restrict__ Ch,
    int M, int N, int K)
{
    extern __shared__ char smc[];
    const uint32_t sb = smem_u32(smc);

    const int tid  = threadIdx.x;
    const int wid  = tid >> 5;
    const int lane = tid & 31;
    const int bm = blockIdx.y << 7;
    const int bn = blockIdx.x << 7;
    const int m0 = (wid & 1) << 6;
    const int n0 = (wid >> 1) << 6;

    // 16B slots for a 128x64 fp16 tile: 1024 -> 8/thread
    int r16[8], k16c[8];
#pragma unroll
    for (int j = 0; j < 8; j++) {
        int s = tid + (j << 7);
        r16[j] = s >> 3;
        k16c[j] = (s & 7) << 3;
    }
    // 8B slots: 2048 -> 16/thread (conv loaders)
    int r8[16], k8c[16];
#pragma unroll
    for (int j = 0; j < 16; j++) {
        int s = tid + (j << 7);
        r8[j] = s >> 4;
        k8c[j] = (s & 15) << 2;
    }

    const uint32_t lrow = (uint32_t)(lane & 15);
    const uint32_t lkq  = (uint32_t)(lane >> 4) * 16;
    uint32_t aOffs[4], bOffs[4];
#pragma unroll
    for (int t = 0; t < 4; t++) {
        aOffs[t] = (uint32_t)(m0 + t * 16 + lrow) * 144 + lkq;
        bOffs[t] = (uint32_t)(n0 + t * 16 + lrow) * 144 + lkq;
    }

    float acc[4][8][4];
#pragma unroll
    for (int i = 0; i < 4; i++)
#pragma unroll
        for (int j = 0; j < 8; j++)
#pragma unroll
            for (int l = 0; l < 4; l++) acc[i][j][l] = 0.f;

    auto gaddrA = [&](int r, int k) -> const __half* {
        if (LOADER == 0) {
            return A + (size_t)(bm + r) * K + k;
        } else if (LOADER == 1) {
            int m = bm + r;
            int b = m >> 8, oy = (m >> 4) & 15, ox = m & 15;
            int ic = k >> 4, ky = (k >> 2) & 3;
            return A + (((size_t)(b * 512 + ic) * 64) + oy * 4 + ky) * 64 + ox * 4;
        } else {
            int m = bm + r;
            int b = m >> 10, oy = (m >> 5) & 31, ox = m & 31;
            int ic = k >> 2;
            return A + (((size_t)(b * 512 + ic) * 64) + oy * 2) * 64 + ox * 2;
        }
    };

    auto issue_chunk = [&](int buf, int k0) {
        const uint32_t bb = sb + (uint32_t)buf * 36864;
        if (LOADER == 0) {
#pragma unroll
            for (int j = 0; j < 8; j++) {
                const uint32_t off = (uint32_t)r16[j] * 144 + (uint32_t)(k16c[j] << 1);
                CP_ASYNC16(bb + off, A + (size_t)(bm + r16[j]) * K + k0 + k16c[j]);
            }
        } else {
#pragma unroll
            for (int j = 0; j < 16; j++) {
                const uint32_t off = (uint32_t)r8[j] * 144 + (uint32_t)(k8c[j] << 1);
                const __half* pa = gaddrA(r8[j], k0 + k8c[j]);
                if (LOADER == 2) {
                    CP_ASYNC4(bb + off,     pa);
                    CP_ASYNC4(bb + off + 4, pa + 64);
                } else {
                    CP_ASYNC8(bb + off, pa);
                }
            }
        }
#pragma unroll
        for (int j = 0; j < 8; j++) {
            const uint32_t off = (uint32_t)r16[j] * 144 + (uint32_t)(k16c[j] << 1);
            CP_ASYNC16(bb + 18432 + off, W + (size_t)(bn + r16[j]) * K + k0 + k16c[j]);
        }
    };

    const int nchunks = K >> 6;
    issue_chunk(0, 0);
    CP_COMMIT();

    for (int c = 0; c < nchunks; c++) {
        const bool more = (c + 1) < nchunks;
        if (more) {
            issue_chunk((c + 1) & 1, (c + 1) << 6);
            CP_COMMIT();
            CP_WAIT1();
        } else {
            CP_WAIT0();
        }
        __syncthreads();

        const uint32_t bb = sb + (uint32_t)(c & 1) * 36864;
        const uint32_t AB = bb, WB = bb + 18432;
        GEMM_CHUNK_BODY64(AB, WB);
        __syncthreads();
    }

    const int gr = lane >> 2;
    const int gc = (lane & 3) * 2;
#pragma unroll
    for (int mt = 0; mt < 4; mt++) {
        const int row0 = bm + m0 + mt * 16 + gr;
#pragma unroll
        for (int nt = 0; nt < 8; nt++) {
            const int col = bn + n0 + nt * 8 + gc;
            float b0 = bias ? bias[col] : 0.f;
            float b1 = bias ? bias[col + 1] : 0.f;
            float o0 = acc[mt][nt][0] + b0, o1 = acc[mt][nt][1] + b1;
            float o2 = acc[mt][nt][2] + b0, o3 = acc[mt][nt][3] + b1;
            if (OUT & 1) {
                *(float2*)(Cmat + (size_t)row0 * N + col) = make_float2(o0, o1);
                *(float2*)(Cmat + (size_t)(row0 + 8) * N + col) = make_float2(o2, o3);
            }
            if (OUT & 2) {
                ((uint32_t*)Ch)[((size_t)row0 * N + col) >> 1] = pack_f16(o0, o1);
                ((uint32_t*)Ch)[((size_t)(row0 + 8) * N + col) >> 1] = pack_f16(o2, o3);
            }
        }
    }
}

// ---------------------------------------------------------------------------
// Merged head-projection GEMM (fp16, 3 sub-problems, one launch, K-chunk 64).
// ---------------------------------------------------------------------------
struct ProjParams {
    const __half *A[3], *W[3];
    float* Cf[3];
    __half* Ch[3];
    int outm[3];
};

__global__ __launch_bounds__(128, 2) void projgemm6_kernel(ProjParams P)
{
    extern __shared__ char smc[];
    const uint32_t sb = smem_u32(smc);
    constexpr int K = 512, N = 256;

    const int y = blockIdx.y;
    const int pi = (y < 64) ? 0 : (y < 192 ? 1 : 2);
    const int ylocal = y - ((pi == 0) ? 0 : (pi == 1) ? 64 : 192);

    const __half* A = P.A[pi];
    const __half* W = P.W[pi];
    float* Cmat = P.Cf[pi];
    __half* Ch = P.Ch[pi];
    const int OUT = P.outm[pi];

    const int tid  = threadIdx.x;
    const int wid  = tid >> 5;
    const int lane = tid & 31;
    const int bm = ylocal << 7;
    const int bn = blockIdx.x << 7;
    const int m0 = (wid & 1) << 6;
    const int n0 = (wid >> 1) << 6;

    int r16[8], k16c[8];
#pragma unroll
    for (int j = 0; j < 8; j++) {
        int s = tid + (j << 7);
        r16[j] = s >> 3;
        k16c[j] = (s & 7) << 3;
    }

    const uint32_t lrow = (uint32_t)(lane & 15);
    const uint32_t lkq  = (uint32_t)(lane >> 4) * 16;
    uint32_t aOffs[4], bOffs[4];
#pragma unroll
    for (int t = 0; t < 4; t++) {
        aOffs[t] = (uint32_t)(m0 + t * 16 + lrow) * 144 + lkq;
        bOffs[t] = (uint32_t)(n0 + t * 16 + lrow) * 144 + lkq;
    }

    float acc[4][8][4];
#pragma unroll
    for (int i = 0; i < 4; i++)
#pragma unroll
        for (int j = 0; j < 8; j++)
#pragma unroll
            for (int l = 0; l < 4; l++) acc[i][j][l] = 0.f;

    auto issue_chunk = [&](int buf, int k0) {
        const uint32_t bb = sb + (uint32_t)buf * 36864;
#pragma unroll
        for (int j = 0; j < 8; j++) {
            const uint32_t off = (uint32_t)r16[j] * 144 + (uint32_t)(k16c[j] << 1);
            const int k = k0 + k16c[j];
            CP_ASYNC16(bb + off,         A + (size_t)(bm + r16[j]) * K + k);
            CP_ASYNC16(bb + 18432 + off, W + (size_t)(bn + r16[j]) * K + k);
        }
    };

    const int nchunks = K >> 6;
    issue_chunk(0, 0);
    CP_COMMIT();

    for (int c = 0; c < nchunks; c++) {
        const bool more = (c + 1) < nchunks;
        if (more) {
            issue_chunk((c + 1) & 1, (c + 1) << 6);
            CP_COMMIT();
            CP_WAIT1();
        } else {
            CP_WAIT0();
        }
        __syncthreads();

        const uint32_t bb = sb + (uint32_t)(c & 1) * 36864;
        const uint32_t AB = bb, WB = bb + 18432;
        GEMM_CHUNK_BODY64(AB, WB);
        __syncthreads();
    }

    const int gr = lane >> 2;
    const int gc = (lane & 3) * 2;
#pragma unroll
    for (int mt = 0; mt < 4; mt++) {
        const int row0 = bm + m0 + mt * 16 + gr;
#pragma unroll
        for (int nt = 0; nt < 8; nt++) {
            const int col = bn + n0 + nt * 8 + gc;
            float o0 = acc[mt][nt][0], o1 = acc[mt][nt][1];
            float o2 = acc[mt][nt][2], o3 = acc[mt][nt][3];
            if (OUT & 1) {
                *(float2*)(Cmat + (size_t)row0 * N + col) = make_float2(o0, o1);
                *(float2*)(Cmat + (size_t)(row0 + 8) * N + col) = make_float2(o2, o3);
            }
            if (OUT & 2) {
                ((uint32_t*)Ch)[((size_t)row0 * N + col) >> 1] = pack_f16(o0, o1);
                ((uint32_t*)Ch)[((size_t)(row0 + 8) * N + col) >> 1] = pack_f16(o2, o3);
            }
        }
    }
}

// ---------------------------------------------------------------------------
// LayerNorm(512) + exact GELU -> fp16 plane
// ---------------------------------------------------------------------------
__global__ void ln_gelu_h_kernel(const float* __restrict__ x,
                                 const float* __restrict__ w,
                                 const float* __restrict__ b,
                                 __half* __restrict__ hO)
{
    __shared__ float sh[8];
    const float* row = x + (size_t)blockIdx.x * 512;
    int t = threadIdx.x;
    float2 v = *(const float2*)(row + t * 2);

    float s = v.x + v.y;
#pragma unroll
    for (int o = 16; o; o >>= 1) s += __shfl_xor_sync(0xffffffffu, s, o);
    if ((t & 31) == 0) sh[t >> 5] = s;
    __syncthreads();
    float tot = 0.f;
#pragma unroll
    for (int i = 0; i < 8; i++) tot += sh[i];
    float mu = tot * (1.f / 512.f);
    float d0 = v.x - mu, d1 = v.y - mu;
    __syncthreads();

    float ss = d0 * d0 + d1 * d1;
#pragma unroll
    for (int o = 16; o; o >>= 1) ss += __shfl_xor_sync(0xffffffffu, ss, o);
    if ((t & 31) == 0) sh[t >> 5] = ss;
    __syncthreads();
    float tot2 = 0.f;
#pragma unroll
    for (int i = 0; i < 8; i++) tot2 += sh[i];
    float inv = rsqrtf(tot2 * (1.f / 512.f) + 1e-5f);

    float y0 = d0 * inv * w[t * 2]     + b[t * 2];
    float y1 = d1 * inv * w[t * 2 + 1] + b[t * 2 + 1];
    y0 = 0.5f * y0 * (1.f + erff(y0 * 0.7071067811865476f));
    y1 = 0.5f * y1 * (1.f + erff(y1 * 0.7071067811865476f));

    ((uint32_t*)hO)[(size_t)blockIdx.x * 256 + t] = pack_f16(y0, y1);
}

// ---------------------------------------------------------------------------
// Depthwise 3x3 (pad 1) residual -> transposed fp16 plane vt[b][c][n]
// ---------------------------------------------------------------------------
__global__ void dwconv_res_th_kernel(const float* __restrict__ v,
                                     const float* __restrict__ lw,
                                     const float* __restrict__ lb,
                                     __half* __restrict__ vtf,
                                     int hh, int ww)
{
    __shared__ float sm[64][65];
    const int Nn = hh * ww;
    const int nt = Nn >> 6;
    int bz = blockIdx.x;
    const int ntile = bz % nt; bz /= nt;
    const int ct = bz & 3;
    const int bb = bz >> 2;
    const int c0 = ct << 6, n0 = ntile << 6;

    const int tid = threadIdx.x;
    const int tc = tid & 63;
    const int tn0 = tid >> 6;
    const int c = c0 + tc;

    float wreg[9];
#pragma unroll
    for (int i = 0; i < 9; i++) wreg[i] = lw[c * 9 + i];
    const float bias = lb[c];

    for (int nn = tn0; nn < 64; nn += 4) {
        const int n = n0 + nn;
        const int y = n / ww;
        const int x = n - y * ww;
        float acc = bias;
#pragma unroll
        for (int dy = -1; dy <= 1; dy++) {
            int yy = y + dy;
            if (yy < 0 || yy >= hh) continue;
#pragma unroll
            for (int dx = -1; dx <= 1; dx++) {
                int xx = x + dx;
                if (xx < 0 || xx >= ww) continue;
                acc += v[((size_t)(bb * Nn + yy * ww + xx) << 8) + c] * wreg[(dy + 1) * 3 + (dx + 1)];
            }
        }
        sm[nn][tc] = v[((size_t)(bb * Nn + n) << 8) + c] + acc;
    }
    __syncthreads();

    const int wc = tid >> 5;
    const int wn = (tid & 31) << 1;
    for (int cc = wc; cc < 64; cc += 8) {
        float v0 = sm[wn][cc], v1 = sm[wn + 1][cc];
        size_t o = (((size_t)(bb * 256 + c0 + cc)) * Nn + n0 + wn) >> 1;
        ((uint32_t*)vtf)[o] = pack_f16(v0, v1);
    }
}

// ---------------------------------------------------------------------------
// Flash attention v3 (fp16 single-pass), unchanged from R14.
// ---------------------------------------------------------------------------
struct FlashB {
    const __half *kp, *vt;
    int Nk, hoff, coloff;
};

__global__ __launch_bounds__(128, 2) void flash3_kernel(
    const __half* __restrict__ qp,
    __half* __restrict__ xf,
    FlashB P0, FlashB P1)
{
    extern __shared__ char smc[];
    const uint32_t sb = smem_u32(smc);
    const uint32_t QB = sb;

    const int tid  = threadIdx.x;
    const int wid  = tid >> 5;
    const int lane = tid & 31;
    const int y = blockIdx.y;
    const FlashB P = (y < 64) ? P0 : P1;
    const int yl = y & 63;
    const int b = yl >> 2;
    const int h = yl & 3;
    const int q0 = blockIdx.x << 7;

    {
        const size_t qbase = ((size_t)(b * Qn + q0)) * 512 + (size_t)(P.hoff + h) * 64;
#pragma unroll
        for (int it = 0; it < 16; it++) {
            int i = tid + (it << 7);
            int row = i >> 4;
            int c4 = (i & 15) << 2;
            CP_ASYNC8(QB + (uint32_t)row * 144 + (uint32_t)(c4 << 1),
                      qp + qbase + (size_t)row * 512 + c4);
        }
        CP_COMMIT();
    }

    auto issue_kv = [&](int buf, int kv0) {
        const uint32_t bb = sb + 18432 + (uint32_t)buf * 18432;
#pragma unroll
        for (int it = 0; it < 8; it++) {
            int i = tid + (it << 7);
            int row = i >> 4;
            int c4 = (i & 15) << 2;
            uint32_t dst = (uint32_t)row * 144 + (uint32_t)(c4 << 1);
            CP_ASYNC8(bb + dst, P.kp + ((size_t)(b * P.Nk + kv0 + row)) * 256 + h * 64 + c4);
            CP_ASYNC8(bb + 9216 + dst, P.vt + ((size_t)(b * 256 + h * 64 + row)) * P.Nk + kv0 + c4);
        }
    };

    const uint32_t lrow = (uint32_t)(lane & 15);
    const uint32_t lkq  = (uint32_t)(lane >> 4) * 16;
    uint32_t qOff[2];
    qOff[0] = ((uint32_t)(wid * 32) + lrow) * 144 + lkq;
    qOff[1] = qOff[0] + 16 * 144;
    const uint32_t kOff = lrow * 144 + lkq;
    const int gr = lane >> 2;

    float m[2][2], l[2][2];
#pragma unroll
    for (int i = 0; i < 2; i++) { m[i][0] = -1e30f; m[i][1] = -1e30f; l[i][0] = 0.f; l[i][1] = 0.f; }
    float Oacc[2][8][4];
#pragma unroll
    for (int i = 0; i < 2; i++)
#pragma unroll
        for (int j = 0; j < 8; j++)
#pragma unroll
            for (int q = 0; q < 4; q++) Oacc[i][j][q] = 0.f;

    const int ntiles = P.Nk >> 6;
    issue_kv(0, 0);
    CP_COMMIT();

    for (int t = 0; t < ntiles; t++) {
        const bool more = (t + 1) < ntiles;
        if (more) {
            issue_kv((t + 1) & 1, (t + 1) << 6);
            CP_COMMIT();
            CP_WAIT1();
        } else {
            CP_WAIT0();
        }
        __syncthreads();

        const uint32_t bb = sb + 18432 + (uint32_t)(t & 1) * 18432;
        const uint32_t KB = bb, VB = bb + 9216;

        float S[2][8][4];
#pragma unroll
        for (int i = 0; i < 2; i++)
#pragma unroll
            for (int j = 0; j < 8; j++)
#pragma unroll
                for (int q = 0; q < 4; q++) S[i][j][q] = 0.f;

#pragma unroll
        for (int ks = 0; ks < 4; ks++) {
            const uint32_t ko = (uint32_t)ks * 32;
            uint32_t qf[2][4];
#pragma unroll
            for (int mt = 0; mt < 2; mt++)
                ldsm_x4(qf[mt][0], qf[mt][1], qf[mt][2], qf[mt][3], QB + qOff[mt] + ko);
#pragma unroll
            for (int g = 0; g < 4; g++) {
                uint32_t kf[4];
                ldsm_x4(kf[0], kf[1], kf[2], kf[3], KB + (uint32_t)g * 2304 + kOff + ko);
#pragma unroll
                for (int mt = 0; mt < 2; mt++) {
                    mma_f16(S[mt][2 * g + 0], qf[mt][0], qf[mt][1], qf[mt][2], qf[mt][3], kf[0], kf[2]);
                    mma_f16(S[mt][2 * g + 1], qf[mt][0], qf[mt][1], qf[mt][2], qf[mt][3], kf[1], kf[3]);
                }
            }
        }

        const float sc = 0.125f;
#pragma unroll
        for (int mt = 0; mt < 2; mt++) {
            float mx0 = m[mt][0], mx1 = m[mt][1];
#pragma unroll
            for (int j = 0; j < 8; j++) {
                S[mt][j][0] *= sc; S[mt][j][1] *= sc; S[mt][j][2] *= sc; S[mt][j][3] *= sc;
                mx0 = fmaxf(mx0, fmaxf(S[mt][j][0], S[mt][j][1]));
                mx1 = fmaxf(mx1, fmaxf(S[mt][j][2], S[mt][j][3]));
            }
#pragma unroll
            for (int o = 1; o <= 2; o <<= 1) {
                mx0 = fmaxf(mx0, __shfl_xor_sync(0xffffffffu, mx0, o));
                mx1 = fmaxf(mx1, __shfl_xor_sync(0xffffffffu, mx1, o));
            }
            const float alpha0 = __expf(m[mt][0] - mx0);
            const float alpha1 = __expf(m[mt][1] - mx1);
            m[mt][0] = mx0; m[mt][1] = mx1;

            float rs0 = 0.f, rs1 = 0.f;
#pragma unroll
            for (int j = 0; j < 8; j++) {
                S[mt][j][0] = __expf(S[mt][j][0] - mx0);
                S[mt][j][1] = __expf(S[mt][j][1] - mx0);
                S[mt][j][2] = __expf(S[mt][j][2] - mx1);
                S[mt][j][3] = __expf(S[mt][j][3] - mx1);
                rs0 += S[mt][j][0] + S[mt][j][1];
                rs1 += S[mt][j][2] + S[mt][j][3];
            }
#pragma unroll
            for (int o = 1; o <= 2; o <<= 1) {
                rs0 += __shfl_xor_sync(0xffffffffu, rs0, o);
                rs1 += __shfl_xor_sync(0xffffffffu, rs1, o);
            }
            l[mt][0] = l[mt][0] * alpha0 + rs0;
            l[mt][1] = l[mt][1] * alpha1 + rs1;

#pragma unroll
            for (int j = 0; j < 8; j++) {
                Oacc[mt][j][0] *= alpha0; Oacc[mt][j][1] *= alpha0;
                Oacc[mt][j][2] *= alpha1; Oacc[mt][j][3] *= alpha1;
            }
        }

#pragma unroll
        for (int t16 = 0; t16 < 4; t16++) {
            uint32_t pf[2][4];
#pragma unroll
            for (int mt = 0; mt < 2; mt++) {
                pf[mt][0] = pack_f16(S[mt][2 * t16][0],     S[mt][2 * t16][1]);
                pf[mt][1] = pack_f16(S[mt][2 * t16][2],     S[mt][2 * t16][3]);
                pf[mt][2] = pack_f16(S[mt][2 * t16 + 1][0], S[mt][2 * t16 + 1][1]);
                pf[mt][3] = pack_f16(S[mt][2 * t16 + 1][2], S[mt][2 * t16 + 1][3]);
            }
            const uint32_t ko = (uint32_t)t16 * 32;
#pragma unroll
            for (int g = 0; g < 4; g++) {
                uint32_t vf[4];
                ldsm_x4(vf[0], vf[1], vf[2], vf[3], VB + (uint32_t)g * 2304 + kOff + ko);
#pragma unroll
                for (int mt = 0; mt < 2; mt++) {
                    mma_f16(Oacc[mt][2 * g + 0], pf[mt][0], pf[mt][1], pf[mt][2], pf[mt][3], vf[0], vf[2]);
                    mma_f16(Oacc[mt][2 * g + 1], pf[mt][0], pf[mt][1], pf[mt][2], pf[mt][3], vf[1], vf[3]);
                }
            }
        }
        __syncthreads();
    }

    const int gc = (lane & 3) * 2;
#pragma unroll
    for (int mt = 0; mt < 2; mt++) {
        const float inv0 = 1.f / l[mt][0];
        const float inv1 = 1.f / l[mt][1];
        const int row0 = b * Qn + q0 + wid * 32 + mt * 16 + gr;
#pragma unroll
        for (int j = 0; j < 8; j++) {
            const int col = P.coloff + h * 64 + (j >> 1) * 16 + (j & 1) * 8 + gc;
            ((uint32_t*)xf)[((size_t)row0 * 512 + col) >> 1] =
                pack_f16(Oacc[mt][j][0] * inv0, Oacc[mt][j][1] * inv0);
            ((uint32_t*)xf)[((size_t)(row0 + 8) * 512 + col) >> 1] =
                pack_f16(Oacc[mt][j][2] * inv1, Oacc[mt][j][3] * inv1);
        }
    }
}

// ---------------------------------------------------------------------------
// Host launch sequence
// ---------------------------------------------------------------------------
extern "C" void kernel_launch(void* const* d_in, const int* in_sizes, int n_in,
                              void* d_out, int out_size)
{
    (void)in_sizes; (void)out_size;
    const int s = (n_in >= 24) ? 2 : 0;

    const float* query   = (const float*)d_in[0];
    const float* key     = (const float*)d_in[1];
    const float* value   = (const float*)d_in[2];
    const float* q_w     = (const float*)d_in[3 + s];
    const float* sr1_w   = (const float*)d_in[4 + s];
    const float* sr1_b   = (const float*)d_in[5 + s];
    const float* norm1_w = (const float*)d_in[6 + s];
    const float* norm1_b = (const float*)d_in[7 + s];
    const float* sr2_w   = (const float*)d_in[8 + s];
    const float* sr2_b   = (const float*)d_in[9 + s];
    const float* norm2_w = (const float*)d_in[10 + s];
    const float* norm2_b = (const float*)d_in[11 + s];
    const float* k1_w    = (const float*)d_in[12 + s];
    const float* k2_w    = (const float*)d_in[14 + s];
    const float* v2_w    = (const float*)d_in[15 + s];
    const float* lc1_w   = (const float*)d_in[16 + s];
    const float* lc1_b   = (const float*)d_in[17 + s];
    const float* lc2_w   = (const float*)d_in[18 + s];
    const float* lc2_b   = (const float*)d_in[19 + s];
    const float* proj_w  = (const float*)d_in[20 + s];
    const float* proj_b  = (const float*)d_in[21 + s];
    float* out = (float*)d_out;

    float *kv1n, *kv2n, *kv1, *v2;
    cudaGetSymbolAddress((void**)&kv1n, g_kv1n);
    cudaGetSymbolAddress((void**)&kv2n, g_kv2n);
    cudaGetSymbolAddress((void**)&kv1,  g_kv1);
    cudaGetSymbolAddress((void**)&v2,   g_v2);

    __half *qf, *qpf, *imgf, *kv1nf, *kv2nf, *k1pf, *k2pf, *vt1f, *vt2f, *xf;
    __half *qwf, *s1wf, *s2wf, *k1wf, *k2wf, *v2wf, *pwf;
    cudaGetSymbolAddress((void**)&qf, g_qf);
    cudaGetSymbolAddress((void**)&qpf, g_qpf);
    cudaGetSymbolAddress((void**)&imgf, g_imgf);
    cudaGetSymbolAddress((void**)&kv1nf, g_kv1nf);
    cudaGetSymbolAddress((void**)&kv2nf, g_kv2nf);
    cudaGetSymbolAddress((void**)&k1pf, g_k1pf);
    cudaGetSymbolAddress((void**)&k2pf, g_k2pf);
    cudaGetSymbolAddress((void**)&vt1f, g_vt1f);
    cudaGetSymbolAddress((void**)&vt2f, g_vt2f);
    cudaGetSymbolAddress((void**)&xf, g_xf);
    cudaGetSymbolAddress((void**)&qwf, g_qwf);
    cudaGetSymbolAddress((void**)&s1wf, g_s1wf);
    cudaGetSymbolAddress((void**)&s2wf, g_s2wf);
    cudaGetSymbolAddress((void**)&k1wf, g_k1wf);
    cudaGetSymbolAddress((void**)&k2wf, g_k2wf);
    cudaGetSymbolAddress((void**)&v2wf, g_v2wf);
    cudaGetSymbolAddress((void**)&pwf, g_pwf);

    const size_t IMG1 = (size_t)B_ * C_ * 64 * 64;
    float* v1 = kv1 + (size_t)B_ * N1_ * C2_;

    const int SMEM6 = 73728;
    cudaFuncSetAttribute(hgemm6_kernel<0, 1>, cudaFuncAttributeMaxDynamicSharedMemorySize, SMEM6);
    cudaFuncSetAttribute(hgemm6_kernel<0, 2>, cudaFuncAttributeMaxDynamicSharedMemorySize, SMEM6);
    cudaFuncSetAttribute(hgemm6_kernel<1, 1>, cudaFuncAttributeMaxDynamicSharedMemorySize, SMEM6);
    cudaFuncSetAttribute(hgemm6_kernel<2, 1>, cudaFuncAttributeMaxDynamicSharedMemorySize, SMEM6);
    cudaFuncSetAttribute(projgemm6_kernel, cudaFuncAttributeMaxDynamicSharedMemorySize, SMEM6);
    const int FSMEM = 55296;
    cudaFuncSetAttribute(flash3_kernel, cudaFuncAttributeMaxDynamicSharedMemorySize, FSMEM);

    dim3 gblk(128);

    // launches ordered so my 4th launch (#6 under ncu -s 5) = sr1 GEMM
    split_h_kernel<<<4096, 256>>>(sr1_w, s1wf);                             // 1
    to_image_h_kernel<<<8192, 256>>>(key, value, imgf, IMG1);               // 2
    split_h_kernel<<<1024, 256>>>(sr2_w, s2wf);                             // 3
    hgemm6_kernel<1, 1><<<dim3(4, 64), gblk, SMEM6>>>(imgf, s1wf, sr1_b,
                                                      kv1n, nullptr, 8192, 512, 8192); // 4 <- profiled

    split_h_kernel<<<256, 256>>>(q_w, qwf);
    split_h_kernel<<<128, 256>>>(k1_w, k1wf);
    split_h_kernel<<<128, 256>>>(k2_w, k2wf);
    split_h_kernel<<<128, 256>>>(v2_w, v2wf);
    split_h_kernel<<<256, 256>>>(proj_w, pwf);
    split_h_kernel<<<8192, 256>>>(query, qf);

    hgemm6_kernel<2, 1><<<dim3(4, 256), gblk, SMEM6>>>(imgf, s2wf, sr2_b,
                                                       kv2n, nullptr, 32768, 512, 2048);

    hgemm6_kernel<0, 2><<<dim3(4, 128), gblk, SMEM6>>>(qf, qwf, nullptr,
                                                       nullptr, qpf, 16384, 512, 512);

    ln_gelu_h_kernel<<<8192,  256>>>(kv1n, norm1_w, norm1_b, kv1nf);
    ln_gelu_h_kernel<<<32768, 256>>>(kv2n, norm2_w, norm2_b, kv2nf);

    {
        ProjParams P;
        P.A[0] = kv1nf;  P.W[0] = k1wf; P.Cf[0] = kv1;     P.Ch[0] = k1pf;    P.outm[0] = 3;
        P.A[1] = kv2nf;  P.W[1] = k2wf; P.Cf[1] = nullptr; P.Ch[1] = k2pf;    P.outm[1] = 2;
        P.A[2] = kv2nf + (size_t)16384 * 512;
        P.W[2] = v2wf;   P.Cf[2] = v2;  P.Ch[2] = nullptr; P.outm[2] = 1;
        projgemm6_kernel<<<dim3(2, 320), gblk, SMEM6>>>(P);
    }

    dwconv_res_th_kernel<<<B_ * 4 * (N1_ / 64), 256>>>(v1, lc1_w, lc1_b, vt1f, 16, 16);
    dwconv_res_th_kernel<<<B_ * 4 * (N2_ / 64), 256>>>(v2, lc2_w, lc2_b, vt2f, 32, 32);

    {
        FlashB P0, P1;
        P0.kp = k1pf; P0.vt = vt1f; P0.Nk = N1_; P0.hoff = 0; P0.coloff = 0;
        P1.kp = k2pf; P1.vt = vt2f; P1.Nk = N2_; P1.hoff = 4; P1.coloff = 256;
        flash3_kernel<<<dim3(8, 128), gblk, FSMEM>>>(qpf, xf, P0, P1);
    }

    hgemm6_kernel<0, 1><<<dim3(4, 128), gblk, SMEM6>>>(xf, pwf, proj_b,
                                                       out, nullptr, 16384, 512, 512);
}

// round 17
// speedup vs baseline: 1.2193x; 1.2193x over previous
#include <cuda_runtime.h>
#include <cuda_fp16.h>
#include <math.h>
#include <stdint.h>

// ---------------------------------------------------------------------------
// Problem constants
// ---------------------------------------------------------------------------
constexpr int B_   = 16;
constexpr int C_   = 512;
constexpr int Qn   = 1024;
constexpr int C2_  = 256;
constexpr int N1_  = 256;
constexpr int N2_  = 1024;

// ---------------------------------------------------------------------------
// Device scratch (fp32 intermediates + fp16 planes)
// ---------------------------------------------------------------------------
__device__ float g_kv1n [(size_t)2 * B_ * N1_ * C_];
__device__ float g_kv2n [(size_t)2 * B_ * N2_ * C_];
__device__ float g_kv1  [(size_t)2 * B_ * N1_ * C2_];
__device__ float g_v2   [(size_t)B_ * N2_ * C2_];

__device__ __half g_qf   [(size_t)16384 * 512];
__device__ __half g_qpf  [(size_t)16384 * 512];
__device__ __half g_imgf [(size_t)2 * B_ * C_ * 64 * 64];
__device__ __half g_kv1nf[(size_t)8192 * 512];
__device__ __half g_kv2nf[(size_t)32768 * 512];
__device__ __half g_k1pf [(size_t)8192 * 256];
__device__ __half g_k2pf [(size_t)16384 * 256];
__device__ __half g_vt1f [(size_t)B_ * C2_ * N1_];
__device__ __half g_vt2f [(size_t)B_ * C2_ * N2_];
__device__ __half g_xf   [(size_t)16384 * 512];
// weights
__device__ __half g_qwf [262144];
__device__ __half g_s1wf[4194304];
__device__ __half g_s2wf[1048576];
__device__ __half g_k1wf[131072];
__device__ __half g_k2wf[131072];
__device__ __half g_v2wf[131072];
__device__ __half g_pwf [262144];

// ---------------------------------------------------------------------------
// helpers
// ---------------------------------------------------------------------------
__device__ __forceinline__ uint32_t smem_u32(const void* p) {
    uint32_t a;
    asm("{ .reg .u64 t; cvta.to.shared.u64 t, %1; cvt.u32.u64 %0, t; }" : "=r"(a) : "l"(p));
    return a;
}
__device__ __forceinline__ void ldsm_x4(uint32_t& r0, uint32_t& r1, uint32_t& r2, uint32_t& r3,
                                        uint32_t addr) {
    asm volatile("ldmatrix.sync.aligned.m8n8.x4.shared.b16 {%0,%1,%2,%3}, [%4];"
                 : "=r"(r0), "=r"(r1), "=r"(r2), "=r"(r3) : "r"(addr));
}
__device__ __forceinline__ void mma_f16(float* d,
                                        uint32_t a0, uint32_t a1, uint32_t a2, uint32_t a3,
                                        uint32_t b0, uint32_t b1) {
    asm volatile(
        "mma.sync.aligned.m16n8k16.row.col.f32.f16.f16.f32 "
        "{%0,%1,%2,%3}, {%4,%5,%6,%7}, {%8,%9}, {%0,%1,%2,%3};"
        : "+f"(d[0]), "+f"(d[1]), "+f"(d[2]), "+f"(d[3])
        : "r"(a0), "r"(a1), "r"(a2), "r"(a3), "r"(b0), "r"(b1));
}
__device__ __forceinline__ uint32_t pack_f16(float x, float y) {
    __half2 p = __floats2half2_rn(x, y);
    return *(uint32_t*)&p;
}

#define CP_ASYNC16(dst, src) \
    asm volatile("cp.async.cg.shared.global [%0], [%1], 16;" :: "r"(dst), "l"(src) : "memory")
#define CP_ASYNC8(dst, src) \
    asm volatile("cp.async.ca.shared.global [%0], [%1], 8;" :: "r"(dst), "l"(src) : "memory")
#define CP_ASYNC4(dst, src) \
    asm volatile("cp.async.ca.shared.global [%0], [%1], 4;" :: "r"(dst), "l"(src) : "memory")
#define CP_COMMIT() asm volatile("cp.async.commit_group;" ::: "memory")
#define CP_WAIT0()  asm volatile("cp.async.wait_group 0;" ::: "memory")
#define CP_WAIT1()  asm volatile("cp.async.wait_group 1;" ::: "memory")

// ---------------------------------------------------------------------------
// fp32 -> fp16 plane (single tensor)
// ---------------------------------------------------------------------------
__global__ void split_h_kernel(const float* __restrict__ src,
                               __half* __restrict__ h)
{
    int i = blockIdx.x * 256 + threadIdx.x;
    float4 v = ((const float4*)src)[i];
    ((uint2*)h)[i] = make_uint2(pack_f16(v.x, v.y), pack_f16(v.z, v.w));
}

// Batched fp32 -> fp16 splits (up to 5 small weight tensors, one launch).
struct SplitBatch {
    const float* src[5];
    __half* dst[5];
    int start[6];            // block-offset prefix (256 float4 per block)
};

__global__ void split_batch_kernel(SplitBatch P)
{
    int bz = blockIdx.x;
    int seg = 0;
#pragma unroll
    for (int t = 1; t < 5; t++) seg += (bz >= P.start[t]) ? 1 : 0;
    int lb = bz - P.start[seg];
    int i = lb * 256 + threadIdx.x;
    float4 v = ((const float4*)P.src[seg])[i];
    ((uint2*)P.dst[seg])[i] = make_uint2(pack_f16(v.x, v.y), pack_f16(v.z, v.w));
}

// ---------------------------------------------------------------------------
// (N,B,C) -> raw-reshape image, fp16 (K + V one launch)
// ---------------------------------------------------------------------------
__global__ void to_image_h_kernel(const float* __restrict__ srcK,
                                  const float* __restrict__ srcV,
                                  __half* __restrict__ h,
                                  size_t img1)
{
    __shared__ float sm[16][513];
    const int half_ = blockIdx.x >> 12;
    const float* src = half_ ? srcV : srcK;
    const size_t dofs = half_ ? img1 : 0;
    size_t base = (size_t)(blockIdx.x & 4095) * 8192;
    for (int j = threadIdx.x; j < 8192; j += 256) sm[j >> 9][j & 511] = src[base + j];
    __syncthreads();
    for (int r = threadIdx.x; r < 8192; r += 256) {
        h[dofs + base + r] = __float2half(sm[r & 15][r >> 4]);
    }
}

// ---------------------------------------------------------------------------
// fp16 HMMA GEMM (R14 configuration): 128 threads, 4 warps of 64x64,
// K-chunk 32, cp.async double buffered.
// LOADER 0: row-major. 1: 4x4/s4 conv im2col. 2: 2x2/s2 conv.
// OUT bit0: fp32 Cmat (+bias); bit1: fp16 plane Ch.
// smem: per buf A 10240 + W 10240 = 20480; double = 40960.
// ---------------------------------------------------------------------------
template <int LOADER, int OUT>
__global__ __launch_bounds__(128, 2) void hgemm4_kernel(
    const __half* __restrict__ A, const __half* __restrict__ W,
    const float* __restrict__ bias, float* __restrict__ Cmat,
    __half* __restrict__ Ch,
    int M, int N, int K)
{
    extern __shared__ char smc[];
    const uint32_t sb = smem_u32(smc);

    const int tid  = threadIdx.x;
    const int wid  = tid >> 5;
    const int lane = tid & 31;
    const int bm = blockIdx.y << 7;
    const int bn = blockIdx.x << 7;
    const int m0 = (wid & 1) << 6;
    const int n0 = (wid >> 1) << 6;

    int rr[8], kk[8];
#pragma unroll
    for (int j = 0; j < 8; j++) {
        int s = tid + (j << 7);
        rr[j] = s >> 3;
        kk[j] = (s & 7) << 2;
    }
    int rw[4], kw[4];
#pragma unroll
    for (int j = 0; j < 4; j++) {
        int s = tid + (j << 7);
        rw[j] = s >> 2;
        kw[j] = (s & 3) << 3;
    }

    const uint32_t lrow = (uint32_t)(lane & 15);
    const uint32_t lkq  = (uint32_t)(lane >> 4) * 16;
    uint32_t aOffs[4], bOffs[4];
#pragma unroll
    for (int t = 0; t < 4; t++) {
        aOffs[t] = (uint32_t)(m0 + t * 16 + lrow) * 80 + lkq;
        bOffs[t] = (uint32_t)(n0 + t * 16 + lrow) * 80 + lkq;
    }

    float acc[4][8][4];
#pragma unroll
    for (int i = 0; i < 4; i++)
#pragma unroll
        for (int j = 0; j < 8; j++)
#pragma unroll
            for (int l = 0; l < 4; l++) acc[i][j][l] = 0.f;

    auto gaddrA = [&](int r, int k) -> const __half* {
        if (LOADER == 0) {
            return A + (size_t)(bm + r) * K + k;
        } else if (LOADER == 1) {
            int m = bm + r;
            int b = m >> 8, oy = (m >> 4) & 15, ox = m & 15;
            int ic = k >> 4, ky = (k >> 2) & 3;
            return A + (((size_t)(b * 512 + ic) * 64) + oy * 4 + ky) * 64 + ox * 4;
        } else {
            int m = bm + r;
            int b = m >> 10, oy = (m >> 5) & 31, ox = m & 31;
            int ic = k >> 2;
            return A + (((size_t)(b * 512 + ic) * 64) + oy * 2) * 64 + ox * 2;
        }
    };

    auto issue_chunk = [&](int buf, int k0) {
        const uint32_t bb = sb + (uint32_t)buf * 20480;
        if (LOADER == 0) {
#pragma unroll
            for (int j = 0; j < 4; j++) {
                const uint32_t off = (uint32_t)rw[j] * 80 + (uint32_t)(kw[j] << 1);
                CP_ASYNC16(bb + off, A + (size_t)(bm + rw[j]) * K + k0 + kw[j]);
            }
        } else {
#pragma unroll
            for (int j = 0; j < 8; j++) {
                const uint32_t off = (uint32_t)rr[j] * 80 + (uint32_t)(kk[j] << 1);
                const __half* pa = gaddrA(rr[j], k0 + kk[j]);
                if (LOADER == 2) {
                    CP_ASYNC4(bb + off,     pa);
                    CP_ASYNC4(bb + off + 4, pa + 64);
                } else {
                    CP_ASYNC8(bb + off, pa);
                }
            }
        }
#pragma unroll
        for (int j = 0; j < 4; j++) {
            const uint32_t off = (uint32_t)rw[j] * 80 + (uint32_t)(kw[j] << 1);
            CP_ASYNC16(bb + 10240 + off, W + (size_t)(bn + rw[j]) * K + k0 + kw[j]);
        }
    };

    const int nchunks = K >> 5;
    issue_chunk(0, 0);
    CP_COMMIT();

    for (int c = 0; c < nchunks; c++) {
        const bool more = (c + 1) < nchunks;
        if (more) {
            issue_chunk((c + 1) & 1, (c + 1) << 5);
            CP_COMMIT();
            CP_WAIT1();
        } else {
            CP_WAIT0();
        }
        __syncthreads();

        const uint32_t bb = sb + (uint32_t)(c & 1) * 20480;
        const uint32_t AB = bb, WB = bb + 10240;
#pragma unroll
        for (int kh = 0; kh < 2; kh++) {
            const uint32_t ko = (uint32_t)kh * 32;
            uint32_t AA[4][4], BB[4][4];
#pragma unroll
            for (int mt = 0; mt < 4; mt++)
                ldsm_x4(AA[mt][0], AA[mt][1], AA[mt][2], AA[mt][3], AB + aOffs[mt] + ko);
#pragma unroll
            for (int nt = 0; nt < 4; nt++)
                ldsm_x4(BB[nt][0], BB[nt][1], BB[nt][2], BB[nt][3], WB + bOffs[nt] + ko);
#pragma unroll
            for (int mt = 0; mt < 4; mt++)
#pragma unroll
                for (int nt = 0; nt < 4; nt++) {
                    mma_f16(acc[mt][2 * nt + 0], AA[mt][0], AA[mt][1], AA[mt][2], AA[mt][3], BB[nt][0], BB[nt][2]);
                    mma_f16(acc[mt][2 * nt + 1], AA[mt][0], AA[mt][1], AA[mt][2], AA[mt][3], BB[nt][1], BB[nt][3]);
                }
        }
        __syncthreads();
    }

    const int gr = lane >> 2;
    const int gc = (lane & 3) * 2;
#pragma unroll
    for (int mt = 0; mt < 4; mt++) {
        const int row0 = bm + m0 + mt * 16 + gr;
#pragma unroll
        for (int nt = 0; nt < 8; nt++) {
            const int col = bn + n0 + nt * 8 + gc;
            float b0 = bias ? bias[col] : 0.f;
            float b1 = bias ? bias[col + 1] : 0.f;
            float o0 = acc[mt][nt][0] + b0, o1 = acc[mt][nt][1] + b1;
            float o2 = acc[mt][nt][2] + b0, o3 = acc[mt][nt][3] + b1;
            if (OUT & 1) {
                *(float2*)(Cmat + (size_t)row0 * N + col) = make_float2(o0, o1);
                *(float2*)(Cmat + (size_t)(row0 + 8) * N + col) = make_float2(o2, o3);
            }
            if (OUT & 2) {
                ((uint32_t*)Ch)[((size_t)row0 * N + col) >> 1] = pack_f16(o0, o1);
                ((uint32_t*)Ch)[((size_t)(row0 + 8) * N + col) >> 1] = pack_f16(o2, o3);
            }
        }
    }
}

// ---------------------------------------------------------------------------
// Merged head-projection GEMM (fp16, 3 sub-problems, one launch, K-chunk 32).
// ---------------------------------------------------------------------------
struct ProjParams {
    const __half *A[3], *W[3];
    float* Cf[3];
    __half* Ch[3];
    int outm[3];
};

__global__ __launch_bounds__(128, 2) void projgemm4_kernel(ProjParams P)
{
    extern __shared__ char smc[];
    const uint32_t sb = smem_u32(smc);
    constexpr int K = 512, N = 256;

    const int y = blockIdx.y;
    const int pi = (y < 64) ? 0 : (y < 192 ? 1 : 2);
    const int ylocal = y - ((pi == 0) ? 0 : (pi == 1) ? 64 : 192);

    const __half* A = P.A[pi];
    const __half* W = P.W[pi];
    float* Cmat = P.Cf[pi];
    __half* Ch = P.Ch[pi];
    const int OUT = P.outm[pi];

    const int tid  = threadIdx.x;
    const int wid  = tid >> 5;
    const int lane = tid & 31;
    const int bm = ylocal << 7;
    const int bn = blockIdx.x << 7;
    const int m0 = (wid & 1) << 6;
    const int n0 = (wid >> 1) << 6;

    int rw[4], kw[4];
#pragma unroll
    for (int j = 0; j < 4; j++) {
        int s = tid + (j << 7);
        rw[j] = s >> 2;
        kw[j] = (s & 3) << 3;
    }

    const uint32_t lrow = (uint32_t)(lane & 15);
    const uint32_t lkq  = (uint32_t)(lane >> 4) * 16;
    uint32_t aOffs[4], bOffs[4];
#pragma unroll
    for (int t = 0; t < 4; t++) {
        aOffs[t] = (uint32_t)(m0 + t * 16 + lrow) * 80 + lkq;
        bOffs[t] = (uint32_t)(n0 + t * 16 + lrow) * 80 + lkq;
    }

    float acc[4][8][4];
#pragma unroll
    for (int i = 0; i < 4; i++)
#pragma unroll
        for (int j = 0; j < 8; j++)
#pragma unroll
            for (int l = 0; l < 4; l++) acc[i][j][l] = 0.f;

    auto issue_chunk = [&](int buf, int k0) {
        const uint32_t bb = sb + (uint32_t)buf * 20480;
#pragma unroll
        for (int j = 0; j < 4; j++) {
            const uint32_t off = (uint32_t)rw[j] * 80 + (uint32_t)(kw[j] << 1);
            const int k = k0 + kw[j];
            CP_ASYNC16(bb + off,         A + (size_t)(bm + rw[j]) * K + k);
            CP_ASYNC16(bb + 10240 + off, W + (size_t)(bn + rw[j]) * K + k);
        }
    };

    const int nchunks = K >> 5;
    issue_chunk(0, 0);
    CP_COMMIT();

    for (int c = 0; c < nchunks; c++) {
        const bool more = (c + 1) < nchunks;
        if (more) {
            issue_chunk((c + 1) & 1, (c + 1) << 5);
            CP_COMMIT();
            CP_WAIT1();
        } else {
            CP_WAIT0();
        }
        __syncthreads();

        const uint32_t bb = sb + (uint32_t)(c & 1) * 20480;
        const uint32_t AB = bb, WB = bb + 10240;
#pragma unroll
        for (int kh = 0; kh < 2; kh++) {
            const uint32_t ko = (uint32_t)kh * 32;
            uint32_t AA[4][4], BB[4][4];
#pragma unroll
            for (int mt = 0; mt < 4; mt++)
                ldsm_x4(AA[mt][0], AA[mt][1], AA[mt][2], AA[mt][3], AB + aOffs[mt] + ko);
#pragma unroll
            for (int nt = 0; nt < 4; nt++)
                ldsm_x4(BB[nt][0], BB[nt][1], BB[nt][2], BB[nt][3], WB + bOffs[nt] + ko);
#pragma unroll
            for (int mt = 0; mt < 4; mt++)
#pragma unroll
                for (int nt = 0; nt < 4; nt++) {
                    mma_f16(acc[mt][2 * nt + 0], AA[mt][0], AA[mt][1], AA[mt][2], AA[mt][3], BB[nt][0], BB[nt][2]);
                    mma_f16(acc[mt][2 * nt + 1], AA[mt][0], AA[mt][1], AA[mt][2], AA[mt][3], BB[nt][1], BB[nt][3]);
                }
        }
        __syncthreads();
    }

    const int gr = lane >> 2;
    const int gc = (lane & 3) * 2;
#pragma unroll
    for (int mt = 0; mt < 4; mt++) {
        const int row0 = bm + m0 + mt * 16 + gr;
#pragma unroll
        for (int nt = 0; nt < 8; nt++) {
            const int col = bn + n0 + nt * 8 + gc;
            float o0 = acc[mt][nt][0], o1 = acc[mt][nt][1];
            float o2 = acc[mt][nt][2], o3 = acc[mt][nt][3];
            if (OUT & 1) {
                *(float2*)(Cmat + (size_t)row0 * N + col) = make_float2(o0, o1);
                *(float2*)(Cmat + (size_t)(row0 + 8) * N + col) = make_float2(o2, o3);
            }
            if (OUT & 2) {
                ((uint32_t*)Ch)[((size_t)row0 * N + col) >> 1] = pack_f16(o0, o1);
                ((uint32_t*)Ch)[((size_t)(row0 + 8) * N + col) >> 1] = pack_f16(o2, o3);
            }
        }
    }
}

// ---------------------------------------------------------------------------
// LayerNorm(512) + exact GELU -> fp16 plane
// ---------------------------------------------------------------------------
__global__ void ln_gelu_h_kernel(const float* __restrict__ x,
                                 const float* __restrict__ w,
                                 const float* __restrict__ b,
                                 __half* __restrict__ hO)
{
    __shared__ float sh[8];
    const float* row = x + (size_t)blockIdx.x * 512;
    int t = threadIdx.x;
    float2 v = *(const float2*)(row + t * 2);

    float s = v.x + v.y;
#pragma unroll
    for (int o = 16; o; o >>= 1) s += __shfl_xor_sync(0xffffffffu, s, o);
    if ((t & 31) == 0) sh[t >> 5] = s;
    __syncthreads();
    float tot = 0.f;
#pragma unroll
    for (int i = 0; i < 8; i++) tot += sh[i];
    float mu = tot * (1.f / 512.f);
    float d0 = v.x - mu, d1 = v.y - mu;
    __syncthreads();

    float ss = d0 * d0 + d1 * d1;
#pragma unroll
    for (int o = 16; o; o >>= 1) ss += __shfl_xor_sync(0xffffffffu, ss, o);
    if ((t & 31) == 0) sh[t >> 5] = ss;
    __syncthreads();
    float tot2 = 0.f;
#pragma unroll
    for (int i = 0; i < 8; i++) tot2 += sh[i];
    float inv = rsqrtf(tot2 * (1.f / 512.f) + 1e-5f);

    float y0 = d0 * inv * w[t * 2]     + b[t * 2];
    float y1 = d1 * inv * w[t * 2 + 1] + b[t * 2 + 1];
    y0 = 0.5f * y0 * (1.f + erff(y0 * 0.7071067811865476f));
    y1 = 0.5f * y1 * (1.f + erff(y1 * 0.7071067811865476f));

    ((uint32_t*)hO)[(size_t)blockIdx.x * 256 + t] = pack_f16(y0, y1);
}

// ---------------------------------------------------------------------------
// Depthwise 3x3 (pad 1) residual -> transposed fp16 plane vt[b][c][n].
// BOTH branches in one launch: blocks [0,256) branch1 (16x16),
// [256,1280) branch2 (32x32).
// ---------------------------------------------------------------------------
__global__ void dwconv_res_th2_kernel(const float* __restrict__ v1,
                                      const float* __restrict__ lw1,
                                      const float* __restrict__ lb1,
                                      __half* __restrict__ vt1,
                                      const float* __restrict__ v2,
                                      const float* __restrict__ lw2,
                                      const float* __restrict__ lb2,
                                      __half* __restrict__ vt2)
{
    __shared__ float sm[64][65];
    const int branch = (blockIdx.x >= 256) ? 1 : 0;
    const float* v  = branch ? v2  : v1;
    const float* lw = branch ? lw2 : lw1;
    const float* lb = branch ? lb2 : lb1;
    __half* vtf     = branch ? vt2 : vt1;
    const int hh = branch ? 32 : 16;
    const int ww = hh;
    const int Nn = hh * ww;
    const int nt = Nn >> 6;

    int bz = blockIdx.x - (branch ? 256 : 0);
    const int ntile = bz % nt; bz /= nt;
    const int ct = bz & 3;
    const int bb = bz >> 2;
    const int c0 = ct << 6, n0 = ntile << 6;

    const int tid = threadIdx.x;
    const int tc = tid & 63;
    const int tn0 = tid >> 6;
    const int c = c0 + tc;

    float wreg[9];
#pragma unroll
    for (int i = 0; i < 9; i++) wreg[i] = lw[c * 9 + i];
    const float bias = lb[c];

    for (int nn = tn0; nn < 64; nn += 4) {
        const int n = n0 + nn;
        const int y = n / ww;
        const int x = n - y * ww;
        float acc = bias;
#pragma unroll
        for (int dy = -1; dy <= 1; dy++) {
            int yy = y + dy;
            if (yy < 0 || yy >= hh) continue;
#pragma unroll
            for (int dx = -1; dx <= 1; dx++) {
                int xx = x + dx;
                if (xx < 0 || xx >= ww) continue;
                acc += v[((size_t)(bb * Nn + yy * ww + xx) << 8) + c] * wreg[(dy + 1) * 3 + (dx + 1)];
            }
        }
        sm[nn][tc] = v[((size_t)(bb * Nn + n) << 8) + c] + acc;
    }
    __syncthreads();

    const int wc = tid >> 5;
    const int wn = (tid & 31) << 1;
    for (int cc = wc; cc < 64; cc += 8) {
        float x0 = sm[wn][cc], x1 = sm[wn + 1][cc];
        size_t o = (((size_t)(bb * 256 + c0 + cc)) * Nn + n0 + wn) >> 1;
        ((uint32_t*)vtf)[o] = pack_f16(x0, x1);
    }
}

// ---------------------------------------------------------------------------
// Flash attention v3 (fp16 single-pass), R14 configuration.
// ---------------------------------------------------------------------------
struct FlashB {
    const __half *kp, *vt;
    int Nk, hoff, coloff;
};

__global__ __launch_bounds__(128, 2) void flash3_kernel(
    const __half* __restrict__ qp,
    __half* __restrict__ xf,
    FlashB P0, FlashB P1)
{
    extern __shared__ char smc[];
    const uint32_t sb = smem_u32(smc);
    const uint32_t QB = sb;

    const int tid  = threadIdx.x;
    const int wid  = tid >> 5;
    const int lane = tid & 31;
    const int y = blockIdx.y;
    const FlashB P = (y < 64) ? P0 : P1;
    const int yl = y & 63;
    const int b = yl >> 2;
    const int h = yl & 3;
    const int q0 = blockIdx.x << 7;

    {
        const size_t qbase = ((size_t)(b * Qn + q0)) * 512 + (size_t)(P.hoff + h) * 64;
#pragma unroll
        for (int it = 0; it < 16; it++) {
            int i = tid + (it << 7);
            int row = i >> 4;
            int c4 = (i & 15) << 2;
            CP_ASYNC8(QB + (uint32_t)row * 144 + (uint32_t)(c4 << 1),
                      qp + qbase + (size_t)row * 512 + c4);
        }
        CP_COMMIT();
    }

    auto issue_kv = [&](int buf, int kv0) {
        const uint32_t bb = sb + 18432 + (uint32_t)buf * 18432;
#pragma unroll
        for (int it = 0; it < 8; it++) {
            int i = tid + (it << 7);
            int row = i >> 4;
            int c4 = (i & 15) << 2;
            uint32_t dst = (uint32_t)row * 144 + (uint32_t)(c4 << 1);
            CP_ASYNC8(bb + dst, P.kp + ((size_t)(b * P.Nk + kv0 + row)) * 256 + h * 64 + c4);
            CP_ASYNC8(bb + 9216 + dst, P.vt + ((size_t)(b * 256 + h * 64 + row)) * P.Nk + kv0 + c4);
        }
    };

    const uint32_t lrow = (uint32_t)(lane & 15);
    const uint32_t lkq  = (uint32_t)(lane >> 4) * 16;
    uint32_t qOff[2];
    qOff[0] = ((uint32_t)(wid * 32) + lrow) * 144 + lkq;
    qOff[1] = qOff[0] + 16 * 144;
    const uint32_t kOff = lrow * 144 + lkq;
    const int gr = lane >> 2;

    float m[2][2], l[2][2];
#pragma unroll
    for (int i = 0; i < 2; i++) { m[i][0] = -1e30f; m[i][1] = -1e30f; l[i][0] = 0.f; l[i][1] = 0.f; }
    float Oacc[2][8][4];
#pragma unroll
    for (int i = 0; i < 2; i++)
#pragma unroll
        for (int j = 0; j < 8; j++)
#pragma unroll
            for (int q = 0; q < 4; q++) Oacc[i][j][q] = 0.f;

    const int ntiles = P.Nk >> 6;
    issue_kv(0, 0);
    CP_COMMIT();

    for (int t = 0; t < ntiles; t++) {
        const bool more = (t + 1) < ntiles;
        if (more) {
            issue_kv((t + 1) & 1, (t + 1) << 6);
            CP_COMMIT();
            CP_WAIT1();
        } else {
            CP_WAIT0();
        }
        __syncthreads();

        const uint32_t bb = sb + 18432 + (uint32_t)(t & 1) * 18432;
        const uint32_t KB = bb, VB = bb + 9216;

        float S[2][8][4];
#pragma unroll
        for (int i = 0; i < 2; i++)
#pragma unroll
            for (int j = 0; j < 8; j++)
#pragma unroll
                for (int q = 0; q < 4; q++) S[i][j][q] = 0.f;

#pragma unroll
        for (int ks = 0; ks < 4; ks++) {
            const uint32_t ko = (uint32_t)ks * 32;
            uint32_t qf[2][4];
#pragma unroll
            for (int mt = 0; mt < 2; mt++)
                ldsm_x4(qf[mt][0], qf[mt][1], qf[mt][2], qf[mt][3], QB + qOff[mt] + ko);
#pragma unroll
            for (int g = 0; g < 4; g++) {
                uint32_t kf[4];
                ldsm_x4(kf[0], kf[1], kf[2], kf[3], KB + (uint32_t)g * 2304 + kOff + ko);
#pragma unroll
                for (int mt = 0; mt < 2; mt++) {
                    mma_f16(S[mt][2 * g + 0], qf[mt][0], qf[mt][1], qf[mt][2], qf[mt][3], kf[0], kf[2]);
                    mma_f16(S[mt][2 * g + 1], qf[mt][0], qf[mt][1], qf[mt][2], qf[mt][3], kf[1], kf[3]);
                }
            }
        }

        const float sc = 0.125f;
#pragma unroll
        for (int mt = 0; mt < 2; mt++) {
            float mx0 = m[mt][0], mx1 = m[mt][1];
#pragma unroll
            for (int j = 0; j < 8; j++) {
                S[mt][j][0] *= sc; S[mt][j][1] *= sc; S[mt][j][2] *= sc; S[mt][j][3] *= sc;
                mx0 = fmaxf(mx0, fmaxf(S[mt][j][0], S[mt][j][1]));
                mx1 = fmaxf(mx1, fmaxf(S[mt][j][2], S[mt][j][3]));
            }
#pragma unroll
            for (int o = 1; o <= 2; o <<= 1) {
                mx0 = fmaxf(mx0, __shfl_xor_sync(0xffffffffu, mx0, o));
                mx1 = fmaxf(mx1, __shfl_xor_sync(0xffffffffu, mx1, o));
            }
            const float alpha0 = __expf(m[mt][0] - mx0);
            const float alpha1 = __expf(m[mt][1] - mx1);
            m[mt][0] = mx0; m[mt][1] = mx1;

            float rs0 = 0.f, rs1 = 0.f;
#pragma unroll
            for (int j = 0; j < 8; j++) {
                S[mt][j][0] = __expf(S[mt][j][0] - mx0);
                S[mt][j][1] = __expf(S[mt][j][1] - mx0);
                S[mt][j][2] = __expf(S[mt][j][2] - mx1);
                S[mt][j][3] = __expf(S[mt][j][3] - mx1);
                rs0 += S[mt][j][0] + S[mt][j][1];
                rs1 += S[mt][j][2] + S[mt][j][3];
            }
#pragma unroll
            for (int o = 1; o <= 2; o <<= 1) {
                rs0 += __shfl_xor_sync(0xffffffffu, rs0, o);
                rs1 += __shfl_xor_sync(0xffffffffu, rs1, o);
            }
            l[mt][0] = l[mt][0] * alpha0 + rs0;
            l[mt][1] = l[mt][1] * alpha1 + rs1;

#pragma unroll
            for (int j = 0; j < 8; j++) {
                Oacc[mt][j][0] *= alpha0; Oacc[mt][j][1] *= alpha0;
                Oacc[mt][j][2] *= alpha1; Oacc[mt][j][3] *= alpha1;
            }
        }

#pragma unroll
        for (int t16 = 0; t16 < 4; t16++) {
            uint32_t pf[2][4];
#pragma unroll
            for (int mt = 0; mt < 2; mt++) {
                pf[mt][0] = pack_f16(S[mt][2 * t16][0],     S[mt][2 * t16][1]);
                pf[mt][1] = pack_f16(S[mt][2 * t16][2],     S[mt][2 * t16][3]);
                pf[mt][2] = pack_f16(S[mt][2 * t16 + 1][0], S[mt][2 * t16 + 1][1]);
                pf[mt][3] = pack_f16(S[mt][2 * t16 + 1][2], S[mt][2 * t16 + 1][3]);
            }
            const uint32_t ko = (uint32_t)t16 * 32;
#pragma unroll
            for (int g = 0; g < 4; g++) {
                uint32_t vf[4];
                ldsm_x4(vf[0], vf[1], vf[2], vf[3], VB + (uint32_t)g * 2304 + kOff + ko);
#pragma unroll
                for (int mt = 0; mt < 2; mt++) {
                    mma_f16(Oacc[mt][2 * g + 0], pf[mt][0], pf[mt][1], pf[mt][2], pf[mt][3], vf[0], vf[2]);
                    mma_f16(Oacc[mt][2 * g + 1], pf[mt][0], pf[mt][1], pf[mt][2], pf[mt][3], vf[1], vf[3]);
                }
            }
        }
        __syncthreads();
    }

    const int gc = (lane & 3) * 2;
#pragma unroll
    for (int mt = 0; mt < 2; mt++) {
        const float inv0 = 1.f / l[mt][0];
        const float inv1 = 1.f / l[mt][1];
        const int row0 = b * Qn + q0 + wid * 32 + mt * 16 + gr;
#pragma unroll
        for (int j = 0; j < 8; j++) {
            const int col = P.coloff + h * 64 + (j >> 1) * 16 + (j & 1) * 8 + gc;
            ((uint32_t*)xf)[((size_t)row0 * 512 + col) >> 1] =
                pack_f16(Oacc[mt][j][0] * inv0, Oacc[mt][j][1] * inv0);
            ((uint32_t*)xf)[((size_t)(row0 + 8) * 512 + col) >> 1] =
                pack_f16(Oacc[mt][j][2] * inv1, Oacc[mt][j][3] * inv1);
        }
    }
}

// ---------------------------------------------------------------------------
// Host launch sequence
// ---------------------------------------------------------------------------
extern "C" void kernel_launch(void* const* d_in, const int* in_sizes, int n_in,
                              void* d_out, int out_size)
{
    (void)in_sizes; (void)out_size;
    const int s = (n_in >= 24) ? 2 : 0;

    const float* query   = (const float*)d_in[0];
    const float* key     = (const float*)d_in[1];
    const float* value   = (const float*)d_in[2];
    const float* q_w     = (const float*)d_in[3 + s];
    const float* sr1_w   = (const float*)d_in[4 + s];
    const float* sr1_b   = (const float*)d_in[5 + s];
    const float* norm1_w = (const float*)d_in[6 + s];
    const float* norm1_b = (const float*)d_in[7 + s];
    const float* sr2_w   = (const float*)d_in[8 + s];
    const float* sr2_b   = (const float*)d_in[9 + s];
    const float* norm2_w = (const float*)d_in[10 + s];
    const float* norm2_b = (const float*)d_in[11 + s];
    const float* k1_w    = (const float*)d_in[12 + s];
    const float* k2_w    = (const float*)d_in[14 + s];
    const float* v2_w    = (const float*)d_in[15 + s];
    const float* lc1_w   = (const float*)d_in[16 + s];
    const float* lc1_b   = (const float*)d_in[17 + s];
    const float* lc2_w   = (const float*)d_in[18 + s];
    const float* lc2_b   = (const float*)d_in[19 + s];
    const float* proj_w  = (const float*)d_in[20 + s];
    const float* proj_b  = (const float*)d_in[21 + s];
    float* out = (float*)d_out;

    float *kv1n, *kv2n, *kv1, *v2;
    cudaGetSymbolAddress((void**)&kv1n, g_kv1n);
    cudaGetSymbolAddress((void**)&kv2n, g_kv2n);
    cudaGetSymbolAddress((void**)&kv1,  g_kv1);
    cudaGetSymbolAddress((void**)&v2,   g_v2);

    __half *qf, *qpf, *imgf, *kv1nf, *kv2nf, *k1pf, *k2pf, *vt1f, *vt2f, *xf;
    __half *qwf, *s1wf, *s2wf, *k1wf, *k2wf, *v2wf, *pwf;
    cudaGetSymbolAddress((void**)&qf, g_qf);
    cudaGetSymbolAddress((void**)&qpf, g_qpf);
    cudaGetSymbolAddress((void**)&imgf, g_imgf);
    cudaGetSymbolAddress((void**)&kv1nf, g_kv1nf);
    cudaGetSymbolAddress((void**)&kv2nf, g_kv2nf);
    cudaGetSymbolAddress((void**)&k1pf, g_k1pf);
    cudaGetSymbolAddress((void**)&k2pf, g_k2pf);
    cudaGetSymbolAddress((void**)&vt1f, g_vt1f);
    cudaGetSymbolAddress((void**)&vt2f, g_vt2f);
    cudaGetSymbolAddress((void**)&xf, g_xf);
    cudaGetSymbolAddress((void**)&qwf, g_qwf);
    cudaGetSymbolAddress((void**)&s1wf, g_s1wf);
    cudaGetSymbolAddress((void**)&s2wf, g_s2wf);
    cudaGetSymbolAddress((void**)&k1wf, g_k1wf);
    cudaGetSymbolAddress((void**)&k2wf, g_k2wf);
    cudaGetSymbolAddress((void**)&v2wf, g_v2wf);
    cudaGetSymbolAddress((void**)&pwf, g_pwf);

    const size_t IMG1 = (size_t)B_ * C_ * 64 * 64;
    float* v1 = kv1 + (size_t)B_ * N1_ * C2_;

    const int SMEM4 = 40960;
    cudaFuncSetAttribute(hgemm4_kernel<0, 1>, cudaFuncAttributeMaxDynamicSharedMemorySize, SMEM4);
    cudaFuncSetAttribute(hgemm4_kernel<0, 2>, cudaFuncAttributeMaxDynamicSharedMemorySize, SMEM4);
    cudaFuncSetAttribute(hgemm4_kernel<1, 1>, cudaFuncAttributeMaxDynamicSharedMemorySize, SMEM4);
    cudaFuncSetAttribute(hgemm4_kernel<2, 1>, cudaFuncAttributeMaxDynamicSharedMemorySize, SMEM4);
    cudaFuncSetAttribute(projgemm4_kernel, cudaFuncAttributeMaxDynamicSharedMemorySize, SMEM4);
    const int FSMEM = 55296;
    cudaFuncSetAttribute(flash3_kernel, cudaFuncAttributeMaxDynamicSharedMemorySize, FSMEM);

    dim3 gblk(128);

    // launches ordered so my 4th launch (#6 under ncu -s 5) = sr1 GEMM
    split_h_kernel<<<4096, 256>>>(sr1_w, s1wf);                             // 1
    to_image_h_kernel<<<8192, 256>>>(key, value, imgf, IMG1);               // 2
    split_h_kernel<<<1024, 256>>>(sr2_w, s2wf);                             // 3
    hgemm4_kernel<1, 1><<<dim3(4, 64), gblk, SMEM4>>>(imgf, s1wf, sr1_b,
                                                      kv1n, nullptr, 8192, 512, 8192); // 4 <- profiled

    // merged small weight splits (q_w 256 | k1 128 | k2 128 | v2 128 | proj 256)
    {
        SplitBatch SB;
        SB.src[0] = q_w;   SB.dst[0] = qwf;
        SB.src[1] = k1_w;  SB.dst[1] = k1wf;
        SB.src[2] = k2_w;  SB.dst[2] = k2wf;
        SB.src[3] = v2_w;  SB.dst[3] = v2wf;
        SB.src[4] = proj_w; SB.dst[4] = pwf;
        SB.start[0] = 0; SB.start[1] = 256; SB.start[2] = 384;
        SB.start[3] = 512; SB.start[4] = 640; SB.start[5] = 896;
        split_batch_kernel<<<896, 256>>>(SB);
    }
    split_h_kernel<<<8192, 256>>>(query, qf);

    hgemm4_kernel<2, 1><<<dim3(4, 256), gblk, SMEM4>>>(imgf, s2wf, sr2_b,
                                                       kv2n, nullptr, 32768, 512, 2048);

    hgemm4_kernel<0, 2><<<dim3(4, 128), gblk, SMEM4>>>(qf, qwf, nullptr,
                                                       nullptr, qpf, 16384, 512, 512);

    ln_gelu_h_kernel<<<8192,  256>>>(kv1n, norm1_w, norm1_b, kv1nf);
    ln_gelu_h_kernel<<<32768, 256>>>(kv2n, norm2_w, norm2_b, kv2nf);

    {
        ProjParams P;
        P.A[0] = kv1nf;  P.W[0] = k1wf; P.Cf[0] = kv1;     P.Ch[0] = k1pf;    P.outm[0] = 3;
        P.A[1] = kv2nf;  P.W[1] = k2wf; P.Cf[1] = nullptr; P.Ch[1] = k2pf;    P.outm[1] = 2;
        P.A[2] = kv2nf + (size_t)16384 * 512;
        P.W[2] = v2wf;   P.Cf[2] = v2;  P.Ch[2] = nullptr; P.outm[2] = 1;
        projgemm4_kernel<<<dim3(2, 320), gblk, SMEM4>>>(P);
    }

    // merged depthwise residual (both branches, one launch)
    dwconv_res_th2_kernel<<<1280, 256>>>(v1, lc1_w, lc1_b, vt1f,
                                         v2, lc2_w, lc2_b, vt2f);

    {
        FlashB P0, P1;
        P0.kp = k1pf; P0.vt = vt1f; P0.Nk = N1_; P0.hoff = 0; P0.coloff = 0;
        P1.kp = k2pf; P1.vt = vt2f; P1.Nk = N2_; P1.hoff = 4; P1.coloff = 256;
        flash3_kernel<<<dim3(8, 128), gblk, FSMEM>>>(qpf, xf, P0, P1);
    }

    hgemm4_kernel<0, 1><<<dim3(4, 128), gblk, SMEM4>>>(xf, pwf, proj_b,
                                                       out, nullptr, 16384, 512, 512);
}